// round 2
// baseline (speedup 1.0000x reference)
#include <cuda_runtime.h>
#include <math.h>

// AttentionST: attention pooling, single pass over embeddings.
// E: [B, S, D] fp32, w_att: [D], w_pred: [D], b_pred: scalar -> out: [B]
// logit[b] = sum_s softmax(E[b]·w_att)[s] * (E[b,s]·w_pred) + b_pred; out = sigmoid(logit)

constexpr int D = 768;
constexpr int S = 512;
constexpr int NTHREADS = 256;
constexpr int NWARPS = NTHREADS / 32;
constexpr int F4_PER_ROW = D / 4;             // 192
constexpr int F4_PER_LANE = F4_PER_ROW / 32;  // 6

__global__ __launch_bounds__(NTHREADS, 4) void attn_pool_kernel(
    const float* __restrict__ E,
    const float* __restrict__ w_att,
    const float* __restrict__ w_pred,
    const float* __restrict__ b_pred,
    float* __restrict__ out)
{
    __shared__ float4 s_wp[F4_PER_ROW];  // w_pred staged in shared (3 KB)
    __shared__ float s_t[S];             // attention scores
    __shared__ float s_p[S];             // per-position pred dot products
    __shared__ float red[2 * NWARPS];

    const int b    = blockIdx.x;
    const int tid  = threadIdx.x;
    const int warp = tid >> 5;
    const int lane = tid & 31;

    // Stage w_pred into shared once per CTA.
    for (int j = tid; j < F4_PER_ROW; j += NTHREADS)
        s_wp[j] = reinterpret_cast<const float4*>(w_pred)[j];

    // Cache each lane's fixed slices of w_att in registers (24 regs).
    float4 wa[F4_PER_LANE];
    #pragma unroll
    for (int j = 0; j < F4_PER_LANE; j++)
        wa[j] = reinterpret_cast<const float4*>(w_att)[j * 32 + lane];

    __syncthreads();

    const float4* Eb = reinterpret_cast<const float4*>(E) + (size_t)b * S * F4_PER_ROW;

    // Pass 1: per-row dual dot products. Warp w handles s = w, w+8, ...
    for (int s = warp; s < S; s += NWARPS) {
        const float4* row = Eb + (size_t)s * F4_PER_ROW;

        // Issue all 6 independent LDG.128 up front for MLP.
        float4 v[F4_PER_LANE];
        #pragma unroll
        for (int j = 0; j < F4_PER_LANE; j++)
            v[j] = row[j * 32 + lane];

        // Dual accumulators per stream to halve the FMA dependency chain.
        float t0 = 0.f, t1 = 0.f, p0 = 0.f, p1 = 0.f;
        #pragma unroll
        for (int j = 0; j < F4_PER_LANE; j++) {
            float4 wp = s_wp[j * 32 + lane];  // conflict-free LDS.128
            t0 = fmaf(v[j].x, wa[j].x, t0);
            t1 = fmaf(v[j].y, wa[j].y, t1);
            t0 = fmaf(v[j].z, wa[j].z, t0);
            t1 = fmaf(v[j].w, wa[j].w, t1);
            p0 = fmaf(v[j].x, wp.x, p0);
            p1 = fmaf(v[j].y, wp.y, p1);
            p0 = fmaf(v[j].z, wp.z, p0);
            p1 = fmaf(v[j].w, wp.w, p1);
        }
        float t = t0 + t1, p = p0 + p1;

        #pragma unroll
        for (int o = 16; o; o >>= 1) {
            t += __shfl_xor_sync(0xffffffffu, t, o);
            p += __shfl_xor_sync(0xffffffffu, p, o);
        }
        if (lane == 0) { s_t[s] = t; s_p[s] = p; }
    }
    __syncthreads();

    // Pass 2: softmax max over scores.
    float m = -INFINITY;
    for (int s = tid; s < S; s += NTHREADS) m = fmaxf(m, s_t[s]);
    #pragma unroll
    for (int o = 16; o; o >>= 1) m = fmaxf(m, __shfl_xor_sync(0xffffffffu, m, o));
    if (lane == 0) red[warp] = m;
    __syncthreads();
    if (warp == 0) {
        float mm = (lane < NWARPS) ? red[lane] : -INFINITY;
        #pragma unroll
        for (int o = 16; o; o >>= 1) mm = fmaxf(mm, __shfl_xor_sync(0xffffffffu, mm, o));
        if (lane == 0) red[0] = mm;
    }
    __syncthreads();
    m = red[0];

    // Pass 3: sum of exp and exp-weighted p.
    float se = 0.f, sep = 0.f;
    for (int s = tid; s < S; s += NTHREADS) {
        float e = __expf(s_t[s] - m);
        se  += e;
        sep += e * s_p[s];
    }
    #pragma unroll
    for (int o = 16; o; o >>= 1) {
        se  += __shfl_xor_sync(0xffffffffu, se, o);
        sep += __shfl_xor_sync(0xffffffffu, sep, o);
    }
    __syncthreads();  // everyone has read red[0] before we overwrite
    if (lane == 0) { red[warp] = se; red[NWARPS + warp] = sep; }
    __syncthreads();
    if (tid == 0) {
        float tse = 0.f, tsep = 0.f;
        #pragma unroll
        for (int w = 0; w < NWARPS; w++) { tse += red[w]; tsep += red[NWARPS + w]; }
        float logit = tsep / tse + b_pred[0];
        out[b] = 1.f / (1.f + __expf(-logit));
    }
}

extern "C" void kernel_launch(void* const* d_in, const int* in_sizes, int n_in,
                              void* d_out, int out_size)
{
    const float* E      = (const float*)d_in[0];
    const float* w_att  = (const float*)d_in[1];
    const float* w_pred = (const float*)d_in[2];
    const float* b_pred = (const float*)d_in[3];
    float* out = (float*)d_out;

    const int B = in_sizes[0] / (S * D);
    attn_pool_kernel<<<B, NTHREADS>>>(E, w_att, w_pred, b_pred, out);
}

// round 3
// speedup vs baseline: 3.2052x; 3.2052x over previous
#include <cuda_runtime.h>
#include <math.h>

// AttentionST: attention pooling, single pass over embeddings.
// E: [B, S, D] fp32, w_att: [D], w_pred: [D], b_pred: scalar -> out: [B]
// logit[b] = sum_s softmax(E[b]·w_att)[s] * (E[b,s]·w_pred) + b_pred; out = sigmoid(logit)

constexpr int D = 768;
constexpr int S = 512;
constexpr int NTHREADS = 256;
constexpr int NWARPS = NTHREADS / 32;
constexpr int F4_PER_ROW = D / 4;             // 192
constexpr int F4_PER_LANE = F4_PER_ROW / 32;  // 6

__global__ __launch_bounds__(NTHREADS, 2) void attn_pool_kernel(
    const float* __restrict__ E,
    const float* __restrict__ w_att,
    const float* __restrict__ w_pred,
    const float* __restrict__ b_pred,
    float* __restrict__ out)
{
    __shared__ float s_t[S];          // attention scores
    __shared__ float s_p[S];          // per-position pred dot products
    __shared__ float red[2 * NWARPS];

    const int b    = blockIdx.x;
    const int tid  = threadIdx.x;
    const int warp = tid >> 5;
    const int lane = tid & 31;

    // Both weight vectors register-resident (48 regs): fixed per lane.
    float4 wa[F4_PER_LANE], wp[F4_PER_LANE];
    #pragma unroll
    for (int j = 0; j < F4_PER_LANE; j++) {
        wa[j] = reinterpret_cast<const float4*>(w_att)[j * 32 + lane];
        wp[j] = reinterpret_cast<const float4*>(w_pred)[j * 32 + lane];
    }

    const float4* Eb = reinterpret_cast<const float4*>(E) + (size_t)b * S * F4_PER_ROW;

    // Pass 1: each warp handles 2 adjacent s-rows per iteration.
    // 12 independent LDG.128 in flight per warp; 4 interleaved reduce chains.
    for (int s = 2 * warp; s < S; s += 2 * NWARPS) {
        const float4* r0 = Eb + (size_t)s * F4_PER_ROW;
        const float4* r1 = r0 + F4_PER_ROW;

        float4 v0[F4_PER_LANE], v1[F4_PER_LANE];
        #pragma unroll
        for (int j = 0; j < F4_PER_LANE; j++) v0[j] = r0[j * 32 + lane];
        #pragma unroll
        for (int j = 0; j < F4_PER_LANE; j++) v1[j] = r1[j * 32 + lane];

        float t0 = 0.f, p0 = 0.f, t1 = 0.f, p1 = 0.f;
        float t0b = 0.f, p0b = 0.f, t1b = 0.f, p1b = 0.f;
        #pragma unroll
        for (int j = 0; j < F4_PER_LANE; j++) {
            t0  = fmaf(v0[j].x, wa[j].x, t0);
            t0b = fmaf(v0[j].y, wa[j].y, t0b);
            t0  = fmaf(v0[j].z, wa[j].z, t0);
            t0b = fmaf(v0[j].w, wa[j].w, t0b);
            p0  = fmaf(v0[j].x, wp[j].x, p0);
            p0b = fmaf(v0[j].y, wp[j].y, p0b);
            p0  = fmaf(v0[j].z, wp[j].z, p0);
            p0b = fmaf(v0[j].w, wp[j].w, p0b);
            t1  = fmaf(v1[j].x, wa[j].x, t1);
            t1b = fmaf(v1[j].y, wa[j].y, t1b);
            t1  = fmaf(v1[j].z, wa[j].z, t1);
            t1b = fmaf(v1[j].w, wa[j].w, t1b);
            p1  = fmaf(v1[j].x, wp[j].x, p1);
            p1b = fmaf(v1[j].y, wp[j].y, p1b);
            p1  = fmaf(v1[j].z, wp[j].z, p1);
            p1b = fmaf(v1[j].w, wp[j].w, p1b);
        }
        t0 += t0b; p0 += p0b; t1 += t1b; p1 += p1b;

        #pragma unroll
        for (int o = 16; o; o >>= 1) {
            t0 += __shfl_xor_sync(0xffffffffu, t0, o);
            p0 += __shfl_xor_sync(0xffffffffu, p0, o);
            t1 += __shfl_xor_sync(0xffffffffu, t1, o);
            p1 += __shfl_xor_sync(0xffffffffu, p1, o);
        }
        if (lane == 0) {
            s_t[s] = t0; s_p[s] = p0;
            s_t[s + 1] = t1; s_p[s + 1] = p1;
        }
    }
    __syncthreads();

    // Pass 2: softmax max over scores.
    float m = -INFINITY;
    for (int s = tid; s < S; s += NTHREADS) m = fmaxf(m, s_t[s]);
    #pragma unroll
    for (int o = 16; o; o >>= 1) m = fmaxf(m, __shfl_xor_sync(0xffffffffu, m, o));
    if (lane == 0) red[warp] = m;
    __syncthreads();
    if (warp == 0) {
        float mm = (lane < NWARPS) ? red[lane] : -INFINITY;
        #pragma unroll
        for (int o = 16; o; o >>= 1) mm = fmaxf(mm, __shfl_xor_sync(0xffffffffu, mm, o));
        if (lane == 0) red[0] = mm;
    }
    __syncthreads();
    m = red[0];

    // Pass 3: sum of exp and exp-weighted p.
    float se = 0.f, sep = 0.f;
    for (int s = tid; s < S; s += NTHREADS) {
        float e = __expf(s_t[s] - m);
        se  += e;
        sep += e * s_p[s];
    }
    #pragma unroll
    for (int o = 16; o; o >>= 1) {
        se  += __shfl_xor_sync(0xffffffffu, se, o);
        sep += __shfl_xor_sync(0xffffffffu, sep, o);
    }
    __syncthreads();  // everyone has read red[0] before we overwrite
    if (lane == 0) { red[warp] = se; red[NWARPS + warp] = sep; }
    __syncthreads();
    if (tid == 0) {
        float tse = 0.f, tsep = 0.f;
        #pragma unroll
        for (int w = 0; w < NWARPS; w++) { tse += red[w]; tsep += red[NWARPS + w]; }
        float logit = tsep / tse + b_pred[0];
        out[b] = 1.f / (1.f + __expf(-logit));
    }
}

extern "C" void kernel_launch(void* const* d_in, const int* in_sizes, int n_in,
                              void* d_out, int out_size)
{
    const float* E      = (const float*)d_in[0];
    const float* w_att  = (const float*)d_in[1];
    const float* w_pred = (const float*)d_in[2];
    const float* b_pred = (const float*)d_in[3];
    float* out = (float*)d_out;

    const int B = in_sizes[0] / (S * D);
    attn_pool_kernel<<<B, NTHREADS>>>(E, w_att, w_pred, b_pred, out);
}